// round 1
// baseline (speedup 1.0000x reference)
#include <cuda_runtime.h>
#include <cstddef>

#define BBATCH 8
#define CCH    256
#define NTOK   4096     // 64*64
#define NG     32
#define CPG    8        // channels per group
#define EPSV   1e-6f

// ---------------- scratch (device globals; no allocation allowed) ----------
__device__ float g_hn[(size_t)BBATCH * CCH * NTOK];
__device__ float g_q [(size_t)BBATCH * CCH * NTOK];
__device__ float g_k [(size_t)BBATCH * CCH * NTOK];
__device__ float g_v [(size_t)BBATCH * CCH * NTOK];
__device__ float g_h [(size_t)BBATCH * CCH * NTOK];
__device__ float g_s [(size_t)BBATCH * NTOK * NTOK];   // 536 MB attention scores

// ---------------- block reductions (blockDim == 256) -----------------------
__device__ __forceinline__ float blk_reduce_sum(float v, float* sh) {
    int lane = threadIdx.x & 31, w = threadIdx.x >> 5;
    #pragma unroll
    for (int o = 16; o; o >>= 1) v += __shfl_xor_sync(0xffffffffu, v, o);
    __syncthreads();
    if (lane == 0) sh[w] = v;
    __syncthreads();
    if (threadIdx.x == 0) {
        float r = 0.f;
        #pragma unroll
        for (int i = 0; i < 8; i++) r += sh[i];
        sh[0] = r;
    }
    __syncthreads();
    return sh[0];
}

__device__ __forceinline__ float blk_reduce_max(float v, float* sh) {
    int lane = threadIdx.x & 31, w = threadIdx.x >> 5;
    #pragma unroll
    for (int o = 16; o; o >>= 1) v = fmaxf(v, __shfl_xor_sync(0xffffffffu, v, o));
    __syncthreads();
    if (lane == 0) sh[w] = v;
    __syncthreads();
    if (threadIdx.x == 0) {
        float r = sh[0];
        #pragma unroll
        for (int i = 1; i < 8; i++) r = fmaxf(r, sh[i]);
        sh[0] = r;
    }
    __syncthreads();
    return sh[0];
}

// ---------------- GroupNorm: one block per (batch, group) ------------------
__global__ __launch_bounds__(256)
void gn_kernel(const float* __restrict__ x, const float* __restrict__ gsc,
               const float* __restrict__ gbi) {
    __shared__ float sh[8];
    int b = blockIdx.x >> 5;
    int g = blockIdx.x & 31;
    const size_t base = ((size_t)b * CCH + (size_t)g * CPG) * NTOK;
    const float* xp = x + base;
    const int total = CPG * NTOK;  // 32768
    float s = 0.f, ss = 0.f;
    for (int i = threadIdx.x; i < total; i += 256) {
        float v = xp[i];
        s += v; ss += v * v;
    }
    s  = blk_reduce_sum(s,  sh);
    ss = blk_reduce_sum(ss, sh);
    const float inv_n = 1.f / (float)total;
    float mean = s * inv_n;
    float var  = ss * inv_n - mean * mean;
    float rstd = rsqrtf(var + EPSV);
    for (int i = threadIdx.x; i < total; i += 256) {
        int c = g * CPG + (i >> 12);          // i / 4096
        g_hn[base + i] = (xp[i] - mean) * rstd * gsc[c] + gbi[c];
    }
}

// ---------------- conv1x1 GEMM: Y[b,o,n] = sum_c W[o,c]*X[b,c,n] + bias ----
// M=256 (o), N=4096 (n), K=256 (c). BM=BN=64, BK=16, 256 threads, 4x4 micro.
__global__ __launch_bounds__(256)
void conv1x1_kernel(const float* __restrict__ W, const float* __restrict__ bias,
                    const float* __restrict__ X, const float* __restrict__ Rres,
                    float* __restrict__ Y) {
    __shared__ __align__(16) float As[16][64];
    __shared__ __align__(16) float Bs[16][64];
    const int b  = blockIdx.z;
    const int m0 = blockIdx.y * 64;
    const int n0 = blockIdx.x * 64;
    const float* Xb = X + (size_t)b * CCH * NTOK;
    float*       Yb = Y + (size_t)b * CCH * NTOK;

    const int t  = threadIdx.x;
    const int ty = t >> 4, tx = t & 15;
    const int arow = t >> 2, acol = (t & 3) * 4;   // A: 64 rows(o) x 16 k
    const int brow = t >> 4, bcol = (t & 15) * 4;  // B: 16 k x 64 cols(n)

    float acc[4][4] = {};
    for (int k0 = 0; k0 < CCH; k0 += 16) {
        float4 a = *(const float4*)&W[(size_t)(m0 + arow) * CCH + k0 + acol];
        As[acol + 0][arow] = a.x; As[acol + 1][arow] = a.y;
        As[acol + 2][arow] = a.z; As[acol + 3][arow] = a.w;
        *(float4*)&Bs[brow][bcol] =
            *(const float4*)&Xb[(size_t)(k0 + brow) * NTOK + n0 + bcol];
        __syncthreads();
        #pragma unroll
        for (int kk = 0; kk < 16; kk++) {
            float4 ra = *(const float4*)&As[kk][ty * 4];
            float4 rb = *(const float4*)&Bs[kk][tx * 4];
            float ra4[4] = {ra.x, ra.y, ra.z, ra.w};
            float rb4[4] = {rb.x, rb.y, rb.z, rb.w};
            #pragma unroll
            for (int i = 0; i < 4; i++)
                #pragma unroll
                for (int j = 0; j < 4; j++)
                    acc[i][j] += ra4[i] * rb4[j];
        }
        __syncthreads();
    }
    #pragma unroll
    for (int i = 0; i < 4; i++) {
        int m = m0 + ty * 4 + i;
        float bv = bias[m];
        #pragma unroll
        for (int j = 0; j < 4; j++) {
            int n = n0 + tx * 4 + j;
            size_t idx = (size_t)m * NTOK + n;
            float v = acc[i][j] + bv;
            if (Rres) v += Rres[(size_t)b * CCH * NTOK + idx];
            Yb[idx] = v;
        }
    }
}

// ---------------- scores: S[b,n,m] = (1/16) * sum_c Q[b,c,n]*K[b,c,m] ------
// M=4096 (n), N=4096 (m), K=256 (c). Both operands K-major in memory.
__global__ __launch_bounds__(256)
void qtk_kernel(const float* __restrict__ Q, const float* __restrict__ K) {
    __shared__ __align__(16) float As[16][64];
    __shared__ __align__(16) float Bs[16][64];
    const int b  = blockIdx.z;
    const int n0 = blockIdx.y * 64;
    const int m0 = blockIdx.x * 64;
    const float* Qb = Q + (size_t)b * CCH * NTOK;
    const float* Kb = K + (size_t)b * CCH * NTOK;
    float*       Sb = g_s + (size_t)b * NTOK * NTOK;

    const int t  = threadIdx.x;
    const int ty = t >> 4, tx = t & 15;
    const int row = t >> 4, col = (t & 15) * 4;    // 16 k-rows x 64 cols

    float acc[4][4] = {};
    for (int k0 = 0; k0 < CCH; k0 += 16) {
        *(float4*)&As[row][col] = *(const float4*)&Qb[(size_t)(k0 + row) * NTOK + n0 + col];
        *(float4*)&Bs[row][col] = *(const float4*)&Kb[(size_t)(k0 + row) * NTOK + m0 + col];
        __syncthreads();
        #pragma unroll
        for (int kk = 0; kk < 16; kk++) {
            float4 ra = *(const float4*)&As[kk][ty * 4];
            float4 rb = *(const float4*)&Bs[kk][tx * 4];
            float ra4[4] = {ra.x, ra.y, ra.z, ra.w};
            float rb4[4] = {rb.x, rb.y, rb.z, rb.w};
            #pragma unroll
            for (int i = 0; i < 4; i++)
                #pragma unroll
                for (int j = 0; j < 4; j++)
                    acc[i][j] += ra4[i] * rb4[j];
        }
        __syncthreads();
    }
    const float scale = 0.0625f;   // 256^-0.5
    #pragma unroll
    for (int i = 0; i < 4; i++)
        #pragma unroll
        for (int j = 0; j < 4; j++)
            Sb[(size_t)(n0 + ty * 4 + i) * NTOK + (m0 + tx * 4 + j)] = acc[i][j] * scale;
}

// ---------------- softmax over m, one block per (b,n) row ------------------
__global__ __launch_bounds__(256)
void softmax_kernel(float* __restrict__ S) {
    __shared__ float sh[8];
    float* p = S + (size_t)blockIdx.x * NTOK;
    float vals[16];
    float mx = -3.4e38f;
    #pragma unroll
    for (int i = 0; i < 16; i++) {
        vals[i] = p[threadIdx.x + i * 256];
        mx = fmaxf(mx, vals[i]);
    }
    mx = blk_reduce_max(mx, sh);
    float sum = 0.f;
    #pragma unroll
    for (int i = 0; i < 16; i++) {
        vals[i] = __expf(vals[i] - mx);
        sum += vals[i];
    }
    sum = blk_reduce_sum(sum, sh);
    float inv = 1.f / sum;
    #pragma unroll
    for (int i = 0; i < 16; i++)
        p[threadIdx.x + i * 256] = vals[i] * inv;
}

// ---------------- h[b,c,n] = sum_m V[b,c,m] * S[b,n,m] ---------------------
// M=256 (c), N=4096 (n), K=4096 (m). NT-style GEMM (both K-contiguous).
__global__ __launch_bounds__(256)
void av_kernel(const float* __restrict__ V) {
    __shared__ __align__(16) float As[16][64];
    __shared__ __align__(16) float Bs[16][64];
    const int b  = blockIdx.z;
    const int c0 = blockIdx.y * 64;
    const int n0 = blockIdx.x * 64;
    const float* Vb = V   + (size_t)b * CCH * NTOK;
    const float* Sb = g_s + (size_t)b * NTOK * NTOK;
    float*       Hb = g_h + (size_t)b * CCH * NTOK;

    const int t  = threadIdx.x;
    const int ty = t >> 4, tx = t & 15;
    const int arow = t >> 2, acol = (t & 3) * 4;   // 64 rows x 16 k

    float acc[4][4] = {};
    for (int k0 = 0; k0 < NTOK; k0 += 16) {
        float4 a = *(const float4*)&Vb[(size_t)(c0 + arow) * NTOK + k0 + acol];
        As[acol + 0][arow] = a.x; As[acol + 1][arow] = a.y;
        As[acol + 2][arow] = a.z; As[acol + 3][arow] = a.w;
        float4 s4 = *(const float4*)&Sb[(size_t)(n0 + arow) * NTOK + k0 + acol];
        Bs[acol + 0][arow] = s4.x; Bs[acol + 1][arow] = s4.y;
        Bs[acol + 2][arow] = s4.z; Bs[acol + 3][arow] = s4.w;
        __syncthreads();
        #pragma unroll
        for (int kk = 0; kk < 16; kk++) {
            float4 ra = *(const float4*)&As[kk][ty * 4];
            float4 rb = *(const float4*)&Bs[kk][tx * 4];
            float ra4[4] = {ra.x, ra.y, ra.z, ra.w};
            float rb4[4] = {rb.x, rb.y, rb.z, rb.w};
            #pragma unroll
            for (int i = 0; i < 4; i++)
                #pragma unroll
                for (int j = 0; j < 4; j++)
                    acc[i][j] += ra4[i] * rb4[j];
        }
        __syncthreads();
    }
    #pragma unroll
    for (int i = 0; i < 4; i++)
        #pragma unroll
        for (int j = 0; j < 4; j++)
            Hb[(size_t)(c0 + ty * 4 + i) * NTOK + (n0 + tx * 4 + j)] = acc[i][j];
}

// ---------------- launch ----------------------------------------------------
extern "C" void kernel_launch(void* const* d_in, const int* in_sizes, int n_in,
                              void* d_out, int out_size) {
    const float* x     = (const float*)d_in[0];
    const float* gns   = (const float*)d_in[1];
    const float* gnb   = (const float*)d_in[2];
    const float* wq    = (const float*)d_in[3];
    const float* bq    = (const float*)d_in[4];
    const float* wk    = (const float*)d_in[5];
    const float* bk    = (const float*)d_in[6];
    const float* wv    = (const float*)d_in[7];
    const float* bv    = (const float*)d_in[8];
    const float* wproj = (const float*)d_in[9];
    const float* bproj = (const float*)d_in[10];
    float* out = (float*)d_out;

    float *hn, *q, *k, *v, *h;
    cudaGetSymbolAddress((void**)&hn, g_hn);
    cudaGetSymbolAddress((void**)&q,  g_q);
    cudaGetSymbolAddress((void**)&k,  g_k);
    cudaGetSymbolAddress((void**)&v,  g_v);
    cudaGetSymbolAddress((void**)&h,  g_h);

    // 1. GroupNorm
    gn_kernel<<<BBATCH * NG, 256>>>(x, gns, gnb);

    // 2. Q, K, V 1x1 convs
    dim3 gw(NTOK / 64, CCH / 64, BBATCH);
    conv1x1_kernel<<<gw, 256>>>(wq, bq, hn, nullptr, q);
    conv1x1_kernel<<<gw, 256>>>(wk, bk, hn, nullptr, k);
    conv1x1_kernel<<<gw, 256>>>(wv, bv, hn, nullptr, v);

    // 3. Scores
    dim3 gs(NTOK / 64, NTOK / 64, BBATCH);
    qtk_kernel<<<gs, 256>>>(q, k);

    // 4. Softmax over keys
    float* s;
    cudaGetSymbolAddress((void**)&s, g_s);
    softmax_kernel<<<BBATCH * NTOK, 256>>>(s);

    // 5. V @ attn^T
    dim3 gv(NTOK / 64, CCH / 64, BBATCH);
    av_kernel<<<gv, 256>>>(v);

    // 6. proj + bias + residual -> d_out
    conv1x1_kernel<<<gw, 256>>>(wproj, bproj, h, x, out);
}

// round 4
// speedup vs baseline: 4.5882x; 4.5882x over previous
#include <cuda_runtime.h>
#include <cuda_bf16.h>
#include <cstddef>
#include <cstdint>

#define BBATCH 8
#define CCH    256
#define NTOK   4096     // 64*64
#define NG     32
#define CPG    8
#define EPSV   1e-6f

typedef __nv_bfloat16 bf16;

// ---------------- scratch (device globals; no allocation allowed) ----------
__device__ bf16  g_hnb[(size_t)BBATCH * CCH * NTOK];   // GN out [c][n]
__device__ bf16  g_hnT[(size_t)BBATCH * NTOK * CCH];   // GN out transposed [n][c]
__device__ bf16  g_qt [(size_t)BBATCH * NTOK * CCH];   // Q^T [n][o]
__device__ bf16  g_kt [(size_t)BBATCH * NTOK * CCH];   // K^T [m][o]
__device__ bf16  g_vb [(size_t)BBATCH * CCH * NTOK];   // V [o][m]
__device__ bf16  g_ht [(size_t)BBATCH * NTOK * CCH];   // attn out^T [n][o]
__device__ float g_s  [(size_t)BBATCH * NTOK * NTOK];  // fp32 scores
__device__ bf16  g_p  [(size_t)BBATCH * NTOK * NTOK];  // bf16 softmax(P)
__device__ bf16  g_wqb[CCH * CCH];
__device__ bf16  g_wkb[CCH * CCH];
__device__ bf16  g_wvb[CCH * CCH];
__device__ bf16  g_wpb[CCH * CCH];

// ================= low-level helpers ========================================
__device__ __forceinline__ uint32_t smem_u32(const void* p) {
    uint32_t a;
    asm("{ .reg .u64 t; cvta.to.shared.u64 t, %1; cvt.u32.u64 %0, t; }" : "=r"(a) : "l"(p));
    return a;
}
__device__ __forceinline__ void cp_async16(uint32_t saddr, const void* gaddr) {
    asm volatile("cp.async.cg.shared.global [%0], [%1], 16;" :: "r"(saddr), "l"(gaddr));
}
#define CP_COMMIT() asm volatile("cp.async.commit_group;" ::: "memory")
#define CP_WAIT(n)  asm volatile("cp.async.wait_group %0;" :: "n"(n) : "memory")

__device__ __forceinline__ void ldsm4(uint32_t* r, uint32_t addr) {
    asm volatile("ldmatrix.sync.aligned.m8n8.x4.shared.b16 {%0,%1,%2,%3}, [%4];"
                 : "=r"(r[0]), "=r"(r[1]), "=r"(r[2]), "=r"(r[3]) : "r"(addr));
}
__device__ __forceinline__ void mma16816(float* c, const uint32_t* a, const uint32_t* b) {
    asm volatile("mma.sync.aligned.m16n8k16.row.col.f32.bf16.bf16.f32 "
                 "{%0,%1,%2,%3}, {%4,%5,%6,%7}, {%8,%9}, {%0,%1,%2,%3};"
                 : "+f"(c[0]), "+f"(c[1]), "+f"(c[2]), "+f"(c[3])
                 : "r"(a[0]), "r"(a[1]), "r"(a[2]), "r"(a[3]),
                   "r"(b[0]), "r"(b[1]));
}

// ---------------- block reductions (blockDim == 256) -----------------------
__device__ __forceinline__ float blk_reduce_sum(float v, float* sh) {
    int lane = threadIdx.x & 31, w = threadIdx.x >> 5;
    #pragma unroll
    for (int o = 16; o; o >>= 1) v += __shfl_xor_sync(0xffffffffu, v, o);
    __syncthreads();
    if (lane == 0) sh[w] = v;
    __syncthreads();
    if (threadIdx.x == 0) {
        float r = 0.f;
        #pragma unroll
        for (int i = 0; i < 8; i++) r += sh[i];
        sh[0] = r;
    }
    __syncthreads();
    return sh[0];
}
__device__ __forceinline__ float blk_reduce_max(float v, float* sh) {
    int lane = threadIdx.x & 31, w = threadIdx.x >> 5;
    #pragma unroll
    for (int o = 16; o; o >>= 1) v = fmaxf(v, __shfl_xor_sync(0xffffffffu, v, o));
    __syncthreads();
    if (lane == 0) sh[w] = v;
    __syncthreads();
    if (threadIdx.x == 0) {
        float r = sh[0];
        #pragma unroll
        for (int i = 1; i < 8; i++) r = fmaxf(r, sh[i]);
        sh[0] = r;
    }
    __syncthreads();
    return sh[0];
}

// ---------------- GroupNorm (bf16 out) --------------------------------------
__global__ __launch_bounds__(256)
void gn_kernel(const float* __restrict__ x, const float* __restrict__ gsc,
               const float* __restrict__ gbi) {
    __shared__ float sh[8];
    int b = blockIdx.x >> 5;
    int g = blockIdx.x & 31;
    const size_t base = ((size_t)b * CCH + (size_t)g * CPG) * NTOK;
    const float* xp = x + base;
    const int total = CPG * NTOK;
    float s = 0.f, ss = 0.f;
    for (int i = threadIdx.x; i < total; i += 256) {
        float v = xp[i];
        s += v; ss += v * v;
    }
    s  = blk_reduce_sum(s,  sh);
    ss = blk_reduce_sum(ss, sh);
    const float inv_n = 1.f / (float)total;
    float mean = s * inv_n;
    float var  = ss * inv_n - mean * mean;
    float rstd = rsqrtf(var + EPSV);
    for (int i = threadIdx.x; i < total; i += 256) {
        int c = g * CPG + (i >> 12);
        g_hnb[base + i] = __float2bfloat16((xp[i] - mean) * rstd * gsc[c] + gbi[c]);
    }
}

// ---------------- bf16 transpose [C][N] -> [N][C] ----------------------------
__global__ __launch_bounds__(256)
void transpose_kernel(const bf16* __restrict__ src, bf16* __restrict__ dst) {
    __shared__ bf16 tile[64][65];
    const int b  = blockIdx.z;
    const int n0 = blockIdx.x * 64;
    const int c0 = blockIdx.y * 64;
    const bf16* sb = src + (size_t)b * CCH * NTOK;
    bf16*       db = dst + (size_t)b * NTOK * CCH;
    const int tx = threadIdx.x & 31, ty = threadIdx.x >> 5;
    #pragma unroll
    for (int j = 0; j < 8; j++) {
        uint32_t v = *(const uint32_t*)&sb[(size_t)(c0 + ty + 8 * j) * NTOK + n0 + tx * 2];
        __nv_bfloat162 v2 = *(__nv_bfloat162*)&v;
        tile[ty + 8 * j][tx * 2 + 0] = v2.x;
        tile[ty + 8 * j][tx * 2 + 1] = v2.y;
    }
    __syncthreads();
    #pragma unroll
    for (int j = 0; j < 8; j++) {
        int n = ty + 8 * j;
        __nv_bfloat162 v2;
        v2.x = tile[tx * 2 + 0][n];
        v2.y = tile[tx * 2 + 1][n];
        *(uint32_t*)&db[(size_t)(n0 + n) * CCH + c0 + tx * 2] = *(uint32_t*)&v2;
    }
}

// ---------------- fp32 -> bf16 elementwise ----------------------------------
__global__ __launch_bounds__(256)
void f2bf_kernel(const float* __restrict__ src, bf16* __restrict__ dst) {
    size_t i = (size_t)blockIdx.x * blockDim.x + threadIdx.x;   // float4 index
    float4 v = ((const float4*)src)[i];
    __nv_bfloat162 lo = __floats2bfloat162_rn(v.x, v.y);
    __nv_bfloat162 hi = __floats2bfloat162_rn(v.z, v.w);
    ((__nv_bfloat162*)dst)[2 * i + 0] = lo;
    ((__nv_bfloat162*)dst)[2 * i + 1] = hi;
}

// ---------------- NT bf16 GEMM: D[r][c] = scale*sum_k A[r][k]B[c][k] + ... ---
// Block tile 128(M) x 128(N) x 32(K). 256 thr = 8 warps (2 M x 4 N).
// Warp tile 64x32: 4 m-frags (16) x 4 n-frags (8). cp.async 2-stage.
#define TILE_ROW 40   // padded row elems (80 B) -> conflict-free ldmatrix
#define STAGE_BYTES (128 * TILE_ROW * 2)

__global__ __launch_bounds__(256, 1)
void mma_gemm(const bf16* __restrict__ A, const bf16* __restrict__ B, void* __restrict__ D,
              size_t aBatch, size_t bBatch, size_t dBatch,
              int astride, int bstride, int dstride, int ksteps, float scale,
              const float* __restrict__ bias, int biasMode,
              const float* __restrict__ resid, int outF32) {
    __shared__ __align__(16) bf16 As[2][128 * TILE_ROW];
    __shared__ __align__(16) bf16 Bs[2][128 * TILE_ROW];
    const uint32_t sA = smem_u32(As);
    const uint32_t sB = smem_u32(Bs);

    const int t    = threadIdx.x;
    const int lane = t & 31;
    const int wid  = t >> 5;
    const int wm   = wid & 1;         // M 64-half
    const int wn   = wid >> 1;        // N 32-quarter
    const int bz   = blockIdx.z;
    const int row0 = blockIdx.y * 128;
    const int col0 = blockIdx.x * 128;

    const bf16* Abase = A + (size_t)bz * aBatch + (size_t)row0 * astride;
    const bf16* Bbase = B + (size_t)bz * bBatch + (size_t)col0 * bstride;

    const int lrow = t >> 2;          // 0..63  (2 iterations cover 128 rows)
    const int lcu  = t & 3;           // 16B chunk within 64B row

    float acc[4][4][4];
    #pragma unroll
    for (int i = 0; i < 4; i++)
        #pragma unroll
        for (int j = 0; j < 4; j++)
            #pragma unroll
            for (int r = 0; r < 4; r++) acc[i][j][r] = 0.f;

    // prologue: stage 0
    {
        const int k0 = 0;
        #pragma unroll
        for (int i = 0; i < 2; i++) {
            int row = lrow + i * 64;
            uint32_t soff = (uint32_t)(row * TILE_ROW + lcu * 8) * 2;
            cp_async16(sA + soff, Abase + (size_t)row * astride + k0 + lcu * 8);
            cp_async16(sB + soff, Bbase + (size_t)row * bstride + k0 + lcu * 8);
        }
        CP_COMMIT();
    }

    for (int kt = 0; kt < ksteps; kt++) {
        if (kt + 1 < ksteps) {
            const int k0 = (kt + 1) * 32;
            const uint32_t st = (uint32_t)((kt + 1) & 1) * STAGE_BYTES;
            #pragma unroll
            for (int i = 0; i < 2; i++) {
                int row = lrow + i * 64;
                uint32_t soff = st + (uint32_t)(row * TILE_ROW + lcu * 8) * 2;
                cp_async16(sA + soff, Abase + (size_t)row * astride + k0 + lcu * 8);
                cp_async16(sB + soff, Bbase + (size_t)row * bstride + k0 + lcu * 8);
            }
            CP_COMMIT();
            CP_WAIT(1);
        } else {
            CP_WAIT(0);
        }
        __syncthreads();

        const uint32_t aB = sA + (uint32_t)(kt & 1) * STAGE_BYTES;
        const uint32_t bB = sB + (uint32_t)(kt & 1) * STAGE_BYTES;
        #pragma unroll
        for (int ks = 0; ks < 2; ks++) {
            uint32_t afr[4][4], bfr[2][4];
            #pragma unroll
            for (int mf = 0; mf < 4; mf++) {
                uint32_t addr = aB + (uint32_t)((wm * 64 + mf * 16 + (lane & 15)) * (TILE_ROW * 2))
                              + (uint32_t)(ks * 32) + ((uint32_t)(lane >> 4) << 4);
                ldsm4(afr[mf], addr);
            }
            #pragma unroll
            for (int ng = 0; ng < 2; ng++) {
                uint32_t addr = bB + (uint32_t)((wn * 32 + ng * 16 + (lane & 7) + ((lane >> 4) & 1) * 8) * (TILE_ROW * 2))
                              + (uint32_t)(ks * 32) + ((uint32_t)((lane >> 3) & 1) << 4);
                ldsm4(bfr[ng], addr);
            }
            #pragma unroll
            for (int mf = 0; mf < 4; mf++)
                #pragma unroll
                for (int nf = 0; nf < 4; nf++)
                    mma16816(acc[mf][nf], afr[mf], &bfr[nf >> 1][(nf & 1) * 2]);
        }
        __syncthreads();
    }

    // epilogue
    const float* residb = resid ? resid + (size_t)bz * dBatch : nullptr;
    #pragma unroll
    for (int mf = 0; mf < 4; mf++) {
        int rbase = row0 + wm * 64 + mf * 16 + (lane >> 2);
        #pragma unroll
        for (int nf = 0; nf < 4; nf++) {
            int c = col0 + wn * 32 + nf * 8 + (lane & 3) * 2;
            #pragma unroll
            for (int h = 0; h < 2; h++) {
                int r = rbase + h * 8;
                float v0 = acc[mf][nf][h * 2 + 0] * scale;
                float v1 = acc[mf][nf][h * 2 + 1] * scale;
                if (biasMode == 1)      { float bv = bias[r]; v0 += bv; v1 += bv; }
                else if (biasMode == 2) { v0 += bias[c]; v1 += bias[c + 1]; }
                size_t idx = (size_t)r * dstride + c;
                if (outF32) {
                    if (residb) { v0 += residb[idx]; v1 += residb[idx + 1]; }
                    float2 f; f.x = v0; f.y = v1;
                    *(float2*)((float*)D + (size_t)bz * dBatch + idx) = f;
                } else {
                    *(__nv_bfloat162*)((bf16*)D + (size_t)bz * dBatch + idx) =
                        __floats2bfloat162_rn(v0, v1);
                }
            }
        }
    }
}

// ---------------- softmax over keys m, write bf16 P --------------------------
__global__ __launch_bounds__(256)
void softmax_kernel(const float* __restrict__ S, bf16* __restrict__ P) {
    __shared__ float sh[8];
    const float* p = S + (size_t)blockIdx.x * NTOK;
    bf16* o = P + (size_t)blockIdx.x * NTOK;
    float vals[16];
    float mx = -3.4e38f;
    #pragma unroll
    for (int i = 0; i < 16; i++) {
        vals[i] = p[threadIdx.x + i * 256];
        mx = fmaxf(mx, vals[i]);
    }
    mx = blk_reduce_max(mx, sh);
    float sum = 0.f;
    #pragma unroll
    for (int i = 0; i < 16; i++) {
        vals[i] = __expf(vals[i] - mx);
        sum += vals[i];
    }
    sum = blk_reduce_sum(sum, sh);
    float inv = 1.f / sum;
    #pragma unroll
    for (int i = 0; i < 16; i++)
        o[threadIdx.x + i * 256] = __float2bfloat16(vals[i] * inv);
}

// ---------------- launch ------------------------------------------------------
extern "C" void kernel_launch(void* const* d_in, const int* in_sizes, int n_in,
                              void* d_out, int out_size) {
    const float* x     = (const float*)d_in[0];
    const float* gns   = (const float*)d_in[1];
    const float* gnb   = (const float*)d_in[2];
    const float* wq    = (const float*)d_in[3];
    const float* bq    = (const float*)d_in[4];
    const float* wk    = (const float*)d_in[5];
    const float* bk    = (const float*)d_in[6];
    const float* wv    = (const float*)d_in[7];
    const float* bv    = (const float*)d_in[8];
    const float* wproj = (const float*)d_in[9];
    const float* bproj = (const float*)d_in[10];
    float* out = (float*)d_out;

    bf16 *hnb, *hnT, *qt, *kt, *vb, *ht, *p, *wqb, *wkb, *wvb, *wpb;
    float *s;
    cudaGetSymbolAddress((void**)&hnb, g_hnb);
    cudaGetSymbolAddress((void**)&hnT, g_hnT);
    cudaGetSymbolAddress((void**)&qt,  g_qt);
    cudaGetSymbolAddress((void**)&kt,  g_kt);
    cudaGetSymbolAddress((void**)&vb,  g_vb);
    cudaGetSymbolAddress((void**)&ht,  g_ht);
    cudaGetSymbolAddress((void**)&s,   g_s);
    cudaGetSymbolAddress((void**)&p,   g_p);
    cudaGetSymbolAddress((void**)&wqb, g_wqb);
    cudaGetSymbolAddress((void**)&wkb, g_wkb);
    cudaGetSymbolAddress((void**)&wvb, g_wvb);
    cudaGetSymbolAddress((void**)&wpb, g_wpb);

    const size_t CN = (size_t)CCH * NTOK;    // 1M elems
    const size_t NN = (size_t)NTOK * NTOK;   // 16M elems

    // 1. GroupNorm -> bf16 [c][n]
    gn_kernel<<<BBATCH * NG, 256>>>(x, gns, gnb);

    // 2. transpose -> hnT [n][c]
    dim3 gt(NTOK / 64, CCH / 64, BBATCH);
    transpose_kernel<<<gt, 256>>>(hnb, hnT);

    // 3. weights -> bf16
    f2bf_kernel<<<64, 256>>>(wq,    wqb);
    f2bf_kernel<<<64, 256>>>(wk,    wkb);
    f2bf_kernel<<<64, 256>>>(wv,    wvb);
    f2bf_kernel<<<64, 256>>>(wproj, wpb);

    // 4. qt[n][o] = hnT . Wq^T + bq   (M=4096, N=256, K=256), bias per-col
    dim3 gq(CCH / 128, NTOK / 128, BBATCH);
    mma_gemm<<<gq, 256>>>(hnT, wqb, qt, CN, 0, CN, CCH, CCH, CCH, CCH / 32, 1.f, bq, 2, nullptr, 0);
    mma_gemm<<<gq, 256>>>(hnT, wkb, kt, CN, 0, CN, CCH, CCH, CCH, CCH / 32, 1.f, bk, 2, nullptr, 0);

    // 5. vb[o][m] = Wv . hnT^T + bv   (M=256, N=4096, K=256), bias per-row
    dim3 gv(NTOK / 128, CCH / 128, BBATCH);
    mma_gemm<<<gv, 256>>>(wvb, hnT, vb, 0, CN, CN, CCH, CCH, NTOK, CCH / 32, 1.f, bv, 1, nullptr, 0);

    // 6. S[n][m] = (1/16) qt . kt^T   (M=4096, N=4096, K=256), fp32 out
    dim3 gs(NTOK / 128, NTOK / 128, BBATCH);
    mma_gemm<<<gs, 256>>>(qt, kt, s, CN, CN, NN, CCH, CCH, NTOK, CCH / 32, 0.0625f,
                          nullptr, 0, nullptr, 1);

    // 7. softmax -> bf16 P
    softmax_kernel<<<BBATCH * NTOK, 256>>>(s, p);

    // 8. ht[n][o] = P . vb^T          (M=4096, N=256, K=4096)
    dim3 gh(CCH / 128, NTOK / 128, BBATCH);
    mma_gemm<<<gh, 256>>>(p, vb, ht, NN, CN, CN, NTOK, NTOK, CCH, NTOK / 32, 1.f,
                          nullptr, 0, nullptr, 0);

    // 9. out[o][n] = Wproj . ht^T + bproj + x   (M=256, N=4096, K=256), fp32 out
    dim3 go(NTOK / 128, CCH / 128, BBATCH);
    mma_gemm<<<go, 256>>>(wpb, ht, out, 0, CN, CN, CCH, CCH, NTOK, CCH / 32, 1.f,
                          bproj, 1, x, 1);
}

// round 8
// speedup vs baseline: 4.8920x; 1.0662x over previous
#include <cuda_runtime.h>
#include <cuda_bf16.h>
#include <cstddef>
#include <cstdint>

#define BBATCH 8
#define CCH    256
#define NTOK   4096     // 64*64
#define NG     32
#define CPG    8
#define EPSV   1e-6f

typedef __nv_bfloat16 bf16;

// ---------------- scratch (device globals; no allocation allowed) ----------
__device__ bf16  g_hnb[(size_t)BBATCH * CCH * NTOK];   // GN out [c][n]
__device__ bf16  g_hnT[(size_t)BBATCH * NTOK * CCH];   // GN out transposed [n][c]
__device__ bf16  g_qt [(size_t)BBATCH * NTOK * CCH];   // Q^T [n][o]
__device__ bf16  g_kt [(size_t)BBATCH * NTOK * CCH];   // K^T [m][o]
__device__ bf16  g_vb [(size_t)BBATCH * CCH * NTOK];   // V [o][m]
__device__ bf16  g_ht [(size_t)BBATCH * NTOK * CCH];   // attn out^T [n][o]
__device__ bf16  g_p  [(size_t)BBATCH * NTOK * NTOK];  // bf16 exp(S) (unnormalized)
__device__ bf16  g_wqb[CCH * CCH];
__device__ bf16  g_wkb[CCH * CCH];
__device__ bf16  g_wvb[CCH * CCH];
__device__ bf16  g_wpb[CCH * CCH];

// ================= low-level helpers ========================================
__device__ __forceinline__ uint32_t smem_u32(const void* p) {
    uint32_t a;
    asm("{ .reg .u64 t; cvta.to.shared.u64 t, %1; cvt.u32.u64 %0, t; }" : "=r"(a) : "l"(p));
    return a;
}
__device__ __forceinline__ void cp_async16(uint32_t saddr, const void* gaddr) {
    asm volatile("cp.async.cg.shared.global [%0], [%1], 16;" :: "r"(saddr), "l"(gaddr));
}
#define CP_COMMIT() asm volatile("cp.async.commit_group;" ::: "memory")
#define CP_WAIT(n)  asm volatile("cp.async.wait_group %0;" :: "n"(n) : "memory")

__device__ __forceinline__ void ldsm4(uint32_t* r, uint32_t addr) {
    asm volatile("ldmatrix.sync.aligned.m8n8.x4.shared.b16 {%0,%1,%2,%3}, [%4];"
                 : "=r"(r[0]), "=r"(r[1]), "=r"(r[2]), "=r"(r[3]) : "r"(addr));
}
__device__ __forceinline__ void mma16816(float* c, const uint32_t* a, const uint32_t* b) {
    asm volatile("mma.sync.aligned.m16n8k16.row.col.f32.bf16.bf16.f32 "
                 "{%0,%1,%2,%3}, {%4,%5,%6,%7}, {%8,%9}, {%0,%1,%2,%3};"
                 : "+f"(c[0]), "+f"(c[1]), "+f"(c[2]), "+f"(c[3])
                 : "r"(a[0]), "r"(a[1]), "r"(a[2]), "r"(a[3]),
                   "r"(b[0]), "r"(b[1]));
}

// ---------------- block reductions (blockDim == 256) -----------------------
__device__ __forceinline__ float blk_reduce_sum(float v, float* sh) {
    int lane = threadIdx.x & 31, w = threadIdx.x >> 5;
    #pragma unroll
    for (int o = 16; o; o >>= 1) v += __shfl_xor_sync(0xffffffffu, v, o);
    __syncthreads();
    if (lane == 0) sh[w] = v;
    __syncthreads();
    if (threadIdx.x == 0) {
        float r = 0.f;
        #pragma unroll
        for (int i = 0; i < 8; i++) r += sh[i];
        sh[0] = r;
    }
    __syncthreads();
    return sh[0];
}

// ---------------- GroupNorm (bf16 out) --------------------------------------
__global__ __launch_bounds__(256)
void gn_kernel(const float* __restrict__ x, const float* __restrict__ gsc,
               const float* __restrict__ gbi) {
    __shared__ float sh[8];
    int b = blockIdx.x >> 5;
    int g = blockIdx.x & 31;
    const size_t base = ((size_t)b * CCH + (size_t)g * CPG) * NTOK;
    const float* xp = x + base;
    const int total = CPG * NTOK;
    float s = 0.f, ss = 0.f;
    for (int i = threadIdx.x; i < total; i += 256) {
        float v = xp[i];
        s += v; ss += v * v;
    }
    s  = blk_reduce_sum(s,  sh);
    ss = blk_reduce_sum(ss, sh);
    const float inv_n = 1.f / (float)total;
    float mean = s * inv_n;
    float var  = ss * inv_n - mean * mean;
    float rstd = rsqrtf(var + EPSV);
    for (int i = threadIdx.x; i < total; i += 256) {
        int c = g * CPG + (i >> 12);
        g_hnb[base + i] = __float2bfloat16((xp[i] - mean) * rstd * gsc[c] + gbi[c]);
    }
}

// ---------------- bf16 transpose [C][N] -> [N][C] ----------------------------
__global__ __launch_bounds__(256)
void transpose_kernel(const bf16* __restrict__ src, bf16* __restrict__ dst) {
    __shared__ bf16 tile[64][65];
    const int b  = blockIdx.z;
    const int n0 = blockIdx.x * 64;
    const int c0 = blockIdx.y * 64;
    const bf16* sb = src + (size_t)b * CCH * NTOK;
    bf16*       db = dst + (size_t)b * NTOK * CCH;
    const int tx = threadIdx.x & 31, ty = threadIdx.x >> 5;
    #pragma unroll
    for (int j = 0; j < 8; j++) {
        uint32_t v = *(const uint32_t*)&sb[(size_t)(c0 + ty + 8 * j) * NTOK + n0 + tx * 2];
        __nv_bfloat162 v2 = *(__nv_bfloat162*)&v;
        tile[ty + 8 * j][tx * 2 + 0] = v2.x;
        tile[ty + 8 * j][tx * 2 + 1] = v2.y;
    }
    __syncthreads();
    #pragma unroll
    for (int j = 0; j < 8; j++) {
        int n = ty + 8 * j;
        __nv_bfloat162 v2;
        v2.x = tile[tx * 2 + 0][n];
        v2.y = tile[tx * 2 + 1][n];
        *(uint32_t*)&db[(size_t)(n0 + n) * CCH + c0 + tx * 2] = *(uint32_t*)&v2;
    }
}

// ---------------- fp32 -> bf16 elementwise ----------------------------------
__global__ __launch_bounds__(256)
void f2bf_kernel(const float* __restrict__ src, bf16* __restrict__ dst) {
    size_t i = (size_t)blockIdx.x * blockDim.x + threadIdx.x;   // float4 index
    float4 v = ((const float4*)src)[i];
    __nv_bfloat162 lo = __floats2bfloat162_rn(v.x, v.y);
    __nv_bfloat162 hi = __floats2bfloat162_rn(v.z, v.w);
    ((__nv_bfloat162*)dst)[2 * i + 0] = lo;
    ((__nv_bfloat162*)dst)[2 * i + 1] = hi;
}

// ---------------- NT bf16 GEMM: D[r][c] = scale*sum_k A[r][k]B[c][k] + ... ---
// Block tile 128(M) x 128(N) x 32(K). 256 thr = 8 warps (2 M x 4 N).
// Warp tile 64x32: 4 m-frags (16) x 4 n-frags (8). cp.async 2-stage.
// expOut: write bf16 exp(scale*acc) (unnormalized softmax numerator).
#define TILE_ROW 40   // padded row elems (80 B) -> conflict-free ldmatrix
#define STAGE_BYTES (128 * TILE_ROW * 2)

__global__ __launch_bounds__(256, 1)
void mma_gemm(const bf16* __restrict__ A, const bf16* __restrict__ B, void* __restrict__ D,
              size_t aBatch, size_t bBatch, size_t dBatch,
              int astride, int bstride, int dstride, int ksteps, float scale,
              const float* __restrict__ bias, int biasMode,
              const float* __restrict__ resid, int outF32, int expOut) {
    __shared__ __align__(16) bf16 As[2][128 * TILE_ROW];
    __shared__ __align__(16) bf16 Bs[2][128 * TILE_ROW];
    const uint32_t sA = smem_u32(As);
    const uint32_t sB = smem_u32(Bs);

    const int t    = threadIdx.x;
    const int lane = t & 31;
    const int wid  = t >> 5;
    const int wm   = wid & 1;
    const int wn   = wid >> 1;
    const int bz   = blockIdx.z;
    const int row0 = blockIdx.y * 128;
    const int col0 = blockIdx.x * 128;

    const bf16* Abase = A + (size_t)bz * aBatch + (size_t)row0 * astride;
    const bf16* Bbase = B + (size_t)bz * bBatch + (size_t)col0 * bstride;

    const int lrow = t >> 2;
    const int lcu  = t & 3;

    float acc[4][4][4];
    #pragma unroll
    for (int i = 0; i < 4; i++)
        #pragma unroll
        for (int j = 0; j < 4; j++)
            #pragma unroll
            for (int r = 0; r < 4; r++) acc[i][j][r] = 0.f;

    {
        #pragma unroll
        for (int i = 0; i < 2; i++) {
            int row = lrow + i * 64;
            uint32_t soff = (uint32_t)(row * TILE_ROW + lcu * 8) * 2;
            cp_async16(sA + soff, Abase + (size_t)row * astride + lcu * 8);
            cp_async16(sB + soff, Bbase + (size_t)row * bstride + lcu * 8);
        }
        CP_COMMIT();
    }

    for (int kt = 0; kt < ksteps; kt++) {
        if (kt + 1 < ksteps) {
            const int k0 = (kt + 1) * 32;
            const uint32_t st = (uint32_t)((kt + 1) & 1) * STAGE_BYTES;
            #pragma unroll
            for (int i = 0; i < 2; i++) {
                int row = lrow + i * 64;
                uint32_t soff = st + (uint32_t)(row * TILE_ROW + lcu * 8) * 2;
                cp_async16(sA + soff, Abase + (size_t)row * astride + k0 + lcu * 8);
                cp_async16(sB + soff, Bbase + (size_t)row * bstride + k0 + lcu * 8);
            }
            CP_COMMIT();
            CP_WAIT(1);
        } else {
            CP_WAIT(0);
        }
        __syncthreads();

        const uint32_t aB = sA + (uint32_t)(kt & 1) * STAGE_BYTES;
        const uint32_t bB = sB + (uint32_t)(kt & 1) * STAGE_BYTES;
        #pragma unroll
        for (int ks = 0; ks < 2; ks++) {
            uint32_t afr[4][4], bfr[2][4];
            #pragma unroll
            for (int mf = 0; mf < 4; mf++) {
                uint32_t addr = aB + (uint32_t)((wm * 64 + mf * 16 + (lane & 15)) * (TILE_ROW * 2))
                              + (uint32_t)(ks * 32) + ((uint32_t)(lane >> 4) << 4);
                ldsm4(afr[mf], addr);
            }
            #pragma unroll
            for (int ng = 0; ng < 2; ng++) {
                uint32_t addr = bB + (uint32_t)((wn * 32 + ng * 16 + (lane & 7) + ((lane >> 4) & 1) * 8) * (TILE_ROW * 2))
                              + (uint32_t)(ks * 32) + ((uint32_t)((lane >> 3) & 1) << 4);
                ldsm4(bfr[ng], addr);
            }
            #pragma unroll
            for (int mf = 0; mf < 4; mf++)
                #pragma unroll
                for (int nf = 0; nf < 4; nf++)
                    mma16816(acc[mf][nf], afr[mf], &bfr[nf >> 1][(nf & 1) * 2]);
        }
        __syncthreads();
    }

    // epilogue
    const float* residb = resid ? resid + (size_t)bz * dBatch : nullptr;
    #pragma unroll
    for (int mf = 0; mf < 4; mf++) {
        int rbase = row0 + wm * 64 + mf * 16 + (lane >> 2);
        #pragma unroll
        for (int nf = 0; nf < 4; nf++) {
            int c = col0 + wn * 32 + nf * 8 + (lane & 3) * 2;
            #pragma unroll
            for (int h = 0; h < 2; h++) {
                int r = rbase + h * 8;
                float v0 = acc[mf][nf][h * 2 + 0] * scale;
                float v1 = acc[mf][nf][h * 2 + 1] * scale;
                if (biasMode == 1)      { float bv = bias[r]; v0 += bv; v1 += bv; }
                else if (biasMode == 2) { v0 += bias[c]; v1 += bias[c + 1]; }
                size_t idx = (size_t)r * dstride + c;
                if (outF32) {
                    if (residb) { v0 += residb[idx]; v1 += residb[idx + 1]; }
                    float2 f; f.x = v0; f.y = v1;
                    *(float2*)((float*)D + (size_t)bz * dBatch + idx) = f;
                } else {
                    if (expOut) { v0 = __expf(v0); v1 = __expf(v1); }
                    *(__nv_bfloat162*)((bf16*)D + (size_t)bz * dBatch + idx) =
                        __floats2bfloat162_rn(v0, v1);
                }
            }
        }
    }
}

// ---------------- AV GEMM with inline row-sum normalization ------------------
// ht[n][o] = (1/rowsum_n) * sum_m expS[n][m] * vb[o][m]
// A = expS [n][m] (astride NTOK), B = vb [o][m] (bstride NTOK), D = ht bf16.
__global__ __launch_bounds__(256, 1)
void mma_av(const bf16* __restrict__ A, const bf16* __restrict__ B, bf16* __restrict__ D) {
    __shared__ __align__(16) bf16 As[2][128 * TILE_ROW];
    __shared__ __align__(16) bf16 Bs[2][128 * TILE_ROW];
    __shared__ float sumrow[128];
    const uint32_t sA = smem_u32(As);
    const uint32_t sB = smem_u32(Bs);

    const int t    = threadIdx.x;
    const int lane = t & 31;
    const int wid  = t >> 5;
    const int wm   = wid & 1;
    const int wn   = wid >> 1;
    const int bz   = blockIdx.z;
    const int row0 = blockIdx.y * 128;
    const int col0 = blockIdx.x * 128;

    const bf16* Abase = A + (size_t)bz * NTOK * NTOK + (size_t)row0 * NTOK;
    const bf16* Bbase = B + (size_t)bz * CCH * NTOK + (size_t)col0 * NTOK;

    const int lrow = t >> 2;
    const int lcu  = t & 3;
    const int ksteps = NTOK / 32;   // 128

    float acc[4][4][4];
    #pragma unroll
    for (int i = 0; i < 4; i++)
        #pragma unroll
        for (int j = 0; j < 4; j++)
            #pragma unroll
            for (int r = 0; r < 4; r++) acc[i][j][r] = 0.f;
    float rs = 0.f;
    const int srow = t >> 1;            // 2 threads per A row for the row sum
    const int skoff = (t & 1) * 16;

    {
        #pragma unroll
        for (int i = 0; i < 2; i++) {
            int row = lrow + i * 64;
            uint32_t soff = (uint32_t)(row * TILE_ROW + lcu * 8) * 2;
            cp_async16(sA + soff, Abase + (size_t)row * NTOK + lcu * 8);
            cp_async16(sB + soff, Bbase + (size_t)row * NTOK + lcu * 8);
        }
        CP_COMMIT();
    }

    for (int kt = 0; kt < ksteps; kt++) {
        if (kt + 1 < ksteps) {
            const int k0 = (kt + 1) * 32;
            const uint32_t st = (uint32_t)((kt + 1) & 1) * STAGE_BYTES;
            #pragma unroll
            for (int i = 0; i < 2; i++) {
                int row = lrow + i * 64;
                uint32_t soff = st + (uint32_t)(row * TILE_ROW + lcu * 8) * 2;
                cp_async16(sA + soff, Abase + (size_t)row * NTOK + k0 + lcu * 8);
                cp_async16(sB + soff, Bbase + (size_t)row * NTOK + k0 + lcu * 8);
            }
            CP_COMMIT();
            CP_WAIT(1);
        } else {
            CP_WAIT(0);
        }
        __syncthreads();

        const uint32_t aB = sA + (uint32_t)(kt & 1) * STAGE_BYTES;
        const uint32_t bB = sB + (uint32_t)(kt & 1) * STAGE_BYTES;
        #pragma unroll
        for (int ks = 0; ks < 2; ks++) {
            uint32_t afr[4][4], bfr[2][4];
            #pragma unroll
            for (int mf = 0; mf < 4; mf++) {
                uint32_t addr = aB + (uint32_t)((wm * 64 + mf * 16 + (lane & 15)) * (TILE_ROW * 2))
                              + (uint32_t)(ks * 32) + ((uint32_t)(lane >> 4) << 4);
                ldsm4(afr[mf], addr);
            }
            #pragma unroll
            for (int ng = 0; ng < 2; ng++) {
                uint32_t addr = bB + (uint32_t)((wn * 32 + ng * 16 + (lane & 7) + ((lane >> 4) & 1) * 8) * (TILE_ROW * 2))
                              + (uint32_t)(ks * 32) + ((uint32_t)((lane >> 3) & 1) << 4);
                ldsm4(bfr[ng], addr);
            }
            #pragma unroll
            for (int mf = 0; mf < 4; mf++)
                #pragma unroll
                for (int nf = 0; nf < 4; nf++)
                    mma16816(acc[mf][nf], afr[mf], &bfr[nf >> 1][(nf & 1) * 2]);
        }

        // inline row-sum of this A (expS) stage: deterministic per-thread order
        {
            const bf16* arow = &As[kt & 1][srow * TILE_ROW + skoff];
            float part = 0.f;
            #pragma unroll
            for (int j = 0; j < 8; j++) {
                __nv_bfloat162 u = *(const __nv_bfloat162*)&arow[2 * j];
                part += __bfloat162float(u.x) + __bfloat162float(u.y);
            }
            rs += part;
        }
        __syncthreads();
    }

    // combine row-sum halves (lanes t, t^1 are adjacent in the same warp)
    rs += __shfl_xor_sync(0xffffffffu, rs, 1);
    if ((t & 1) == 0) sumrow[srow] = rs;
    __syncthreads();

    // epilogue: normalize rows, write bf16
    bf16* Db = D + (size_t)bz * NTOK * CCH;
    #pragma unroll
    for (int mf = 0; mf < 4; mf++) {
        int rloc = wm * 64 + mf * 16 + (lane >> 2);
        #pragma unroll
        for (int nf = 0; nf < 4; nf++) {
            int c = col0 + wn * 32 + nf * 8 + (lane & 3) * 2;
            #pragma unroll
            for (int h = 0; h < 2; h++) {
                int rl = rloc + h * 8;
                float inv = 1.f / sumrow[rl];
                float v0 = acc[mf][nf][h * 2 + 0] * inv;
                float v1 = acc[mf][nf][h * 2 + 1] * inv;
                *(__nv_bfloat162*)&Db[(size_t)(row0 + rl) * CCH + c] =
                    __floats2bfloat162_rn(v0, v1);
            }
        }
    }
}

// ---------------- launch ------------------------------------------------------
extern "C" void kernel_launch(void* const* d_in, const int* in_sizes, int n_in,
                              void* d_out, int out_size) {
    const float* x     = (const float*)d_in[0];
    const float* gns   = (const float*)d_in[1];
    const float* gnb   = (const float*)d_in[2];
    const float* wq    = (const float*)d_in[3];
    const float* bq    = (const float*)d_in[4];
    const float* wk    = (const float*)d_in[5];
    const float* bk    = (const float*)d_in[6];
    const float* wv    = (const float*)d_in[7];
    const float* bv    = (const float*)d_in[8];
    const float* wproj = (const float*)d_in[9];
    const float* bproj = (const float*)d_in[10];
    float* out = (float*)d_out;

    bf16 *hnb, *hnT, *qt, *kt, *vb, *ht, *p, *wqb, *wkb, *wvb, *wpb;
    cudaGetSymbolAddress((void**)&hnb, g_hnb);
    cudaGetSymbolAddress((void**)&hnT, g_hnT);
    cudaGetSymbolAddress((void**)&qt,  g_qt);
    cudaGetSymbolAddress((void**)&kt,  g_kt);
    cudaGetSymbolAddress((void**)&vb,  g_vb);
    cudaGetSymbolAddress((void**)&ht,  g_ht);
    cudaGetSymbolAddress((void**)&p,   g_p);
    cudaGetSymbolAddress((void**)&wqb, g_wqb);
    cudaGetSymbolAddress((void**)&wkb, g_wkb);
    cudaGetSymbolAddress((void**)&wvb, g_wvb);
    cudaGetSymbolAddress((void**)&wpb, g_wpb);

    const size_t CN = (size_t)CCH * NTOK;
    const size_t NN = (size_t)NTOK * NTOK;

    // 1. GroupNorm -> bf16 [c][n]
    gn_kernel<<<BBATCH * NG, 256>>>(x, gns, gnb);

    // 2. transpose -> hnT [n][c]
    dim3 gt(NTOK / 64, CCH / 64, BBATCH);
    transpose_kernel<<<gt, 256>>>(hnb, hnT);

    // 3. weights -> bf16
    f2bf_kernel<<<64, 256>>>(wq,    wqb);
    f2bf_kernel<<<64, 256>>>(wk,    wkb);
    f2bf_kernel<<<64, 256>>>(wv,    wvb);
    f2bf_kernel<<<64, 256>>>(wproj, wpb);

    // 4. qt[n][o] = hnT . Wq^T + bq   (bias per-col)
    dim3 gq(CCH / 128, NTOK / 128, BBATCH);
    mma_gemm<<<gq, 256>>>(hnT, wqb, qt, CN, 0, CN, CCH, CCH, CCH, CCH / 32, 1.f, bq, 2, nullptr, 0, 0);
    mma_gemm<<<gq, 256>>>(hnT, wkb, kt, CN, 0, CN, CCH, CCH, CCH, CCH / 32, 1.f, bk, 2, nullptr, 0, 0);

    // 5. vb[o][m] = Wv . hnT^T + bv   (bias per-row)
    dim3 gv(NTOK / 128, CCH / 128, BBATCH);
    mma_gemm<<<gv, 256>>>(wvb, hnT, vb, 0, CN, CN, CCH, CCH, NTOK, CCH / 32, 1.f, bv, 1, nullptr, 0, 0);

    // 6. expS[n][m] = exp((1/16) qt . kt^T)  -> bf16, no softmax kernel needed
    dim3 gs(NTOK / 128, NTOK / 128, BBATCH);
    mma_gemm<<<gs, 256>>>(qt, kt, p, CN, CN, NN, CCH, CCH, NTOK, CCH / 32, 0.0625f,
                          nullptr, 0, nullptr, 0, 1);

    // 7. ht[n][o] = softmax-normalized expS . vb^T  (row sums inline)
    dim3 gh(CCH / 128, NTOK / 128, BBATCH);
    mma_av<<<gh, 256>>>(p, vb, ht);

    // 8. out[o][n] = Wproj . ht^T + bproj + x   (fp32 out + residual)
    dim3 go(NTOK / 128, CCH / 128, BBATCH);
    mma_gemm<<<go, 256>>>(wpb, ht, out, 0, CN, CN, CCH, CCH, NTOK, CCH / 32, 1.f,
                          bproj, 1, x, 1, 0);
}

// round 9
// speedup vs baseline: 4.9897x; 1.0200x over previous
#include <cuda_runtime.h>
#include <cuda_bf16.h>
#include <cstddef>
#include <cstdint>

#define BBATCH 8
#define CCH    256
#define NTOK   4096     // 64*64
#define NG     32
#define CPG    8
#define EPSV   1e-6f

typedef __nv_bfloat16 bf16;

// ---------------- scratch (device globals; no allocation allowed) ----------
__device__ bf16  g_hnb[(size_t)BBATCH * CCH * NTOK];   // GN out [c][n]
__device__ bf16  g_hnT[(size_t)BBATCH * NTOK * CCH];   // GN out transposed [n][c]
__device__ bf16  g_qt [(size_t)BBATCH * NTOK * CCH];   // Q^T [n][o]
__device__ bf16  g_kt [(size_t)BBATCH * NTOK * CCH];   // K^T [m][o]
__device__ bf16  g_vb [(size_t)BBATCH * CCH * NTOK];   // V [o][m]
__device__ bf16  g_ht [(size_t)BBATCH * NTOK * CCH];   // attn out^T [n][o]
__device__ bf16  g_p  [(size_t)BBATCH * NTOK * NTOK];  // bf16 exp(S) (unnormalized)
__device__ bf16  g_wqb[CCH * CCH];
__device__ bf16  g_wkb[CCH * CCH];
__device__ bf16  g_wvb[CCH * CCH];
__device__ bf16  g_wpb[CCH * CCH];

// ================= low-level helpers ========================================
__device__ __forceinline__ uint32_t smem_u32(const void* p) {
    uint32_t a;
    asm("{ .reg .u64 t; cvta.to.shared.u64 t, %1; cvt.u32.u64 %0, t; }" : "=r"(a) : "l"(p));
    return a;
}
__device__ __forceinline__ void cp_async16(uint32_t saddr, const void* gaddr) {
    asm volatile("cp.async.cg.shared.global [%0], [%1], 16;" :: "r"(saddr), "l"(gaddr));
}
#define CP_COMMIT() asm volatile("cp.async.commit_group;" ::: "memory")
#define CP_WAIT(n)  asm volatile("cp.async.wait_group %0;" :: "n"(n) : "memory")

__device__ __forceinline__ void ldsm4(uint32_t* r, uint32_t addr) {
    asm volatile("ldmatrix.sync.aligned.m8n8.x4.shared.b16 {%0,%1,%2,%3}, [%4];"
                 : "=r"(r[0]), "=r"(r[1]), "=r"(r[2]), "=r"(r[3]) : "r"(addr));
}
__device__ __forceinline__ void mma16816(float* c, const uint32_t* a, const uint32_t* b) {
    asm volatile("mma.sync.aligned.m16n8k16.row.col.f32.bf16.bf16.f32 "
                 "{%0,%1,%2,%3}, {%4,%5,%6,%7}, {%8,%9}, {%0,%1,%2,%3};"
                 : "+f"(c[0]), "+f"(c[1]), "+f"(c[2]), "+f"(c[3])
                 : "r"(a[0]), "r"(a[1]), "r"(a[2]), "r"(a[3]),
                   "r"(b[0]), "r"(b[1]));
}

// ---------------- block reductions (blockDim == 256) -----------------------
__device__ __forceinline__ float blk_reduce_sum(float v, float* sh) {
    int lane = threadIdx.x & 31, w = threadIdx.x >> 5;
    #pragma unroll
    for (int o = 16; o; o >>= 1) v += __shfl_xor_sync(0xffffffffu, v, o);
    __syncthreads();
    if (lane == 0) sh[w] = v;
    __syncthreads();
    if (threadIdx.x == 0) {
        float r = 0.f;
        #pragma unroll
        for (int i = 0; i < 8; i++) r += sh[i];
        sh[0] = r;
    }
    __syncthreads();
    return sh[0];
}

// ---------------- GroupNorm (bf16 out) --------------------------------------
__global__ __launch_bounds__(256)
void gn_kernel(const float* __restrict__ x, const float* __restrict__ gsc,
               const float* __restrict__ gbi) {
    __shared__ float sh[8];
    int b = blockIdx.x >> 5;
    int g = blockIdx.x & 31;
    const size_t base = ((size_t)b * CCH + (size_t)g * CPG) * NTOK;
    const float* xp = x + base;
    const int total = CPG * NTOK;
    float s = 0.f, ss = 0.f;
    for (int i = threadIdx.x; i < total; i += 256) {
        float v = xp[i];
        s += v; ss += v * v;
    }
    s  = blk_reduce_sum(s,  sh);
    ss = blk_reduce_sum(ss, sh);
    const float inv_n = 1.f / (float)total;
    float mean = s * inv_n;
    float var  = ss * inv_n - mean * mean;
    float rstd = rsqrtf(var + EPSV);
    for (int i = threadIdx.x; i < total; i += 256) {
        int c = g * CPG + (i >> 12);
        g_hnb[base + i] = __float2bfloat16((xp[i] - mean) * rstd * gsc[c] + gbi[c]);
    }
}

// ---------------- bf16 transpose [C][N] -> [N][C] ----------------------------
__global__ __launch_bounds__(256)
void transpose_kernel(const bf16* __restrict__ src, bf16* __restrict__ dst) {
    __shared__ bf16 tile[64][65];
    const int b  = blockIdx.z;
    const int n0 = blockIdx.x * 64;
    const int c0 = blockIdx.y * 64;
    const bf16* sb = src + (size_t)b * CCH * NTOK;
    bf16*       db = dst + (size_t)b * NTOK * CCH;
    const int tx = threadIdx.x & 31, ty = threadIdx.x >> 5;
    #pragma unroll
    for (int j = 0; j < 8; j++) {
        uint32_t v = *(const uint32_t*)&sb[(size_t)(c0 + ty + 8 * j) * NTOK + n0 + tx * 2];
        __nv_bfloat162 v2 = *(__nv_bfloat162*)&v;
        tile[ty + 8 * j][tx * 2 + 0] = v2.x;
        tile[ty + 8 * j][tx * 2 + 1] = v2.y;
    }
    __syncthreads();
    #pragma unroll
    for (int j = 0; j < 8; j++) {
        int n = ty + 8 * j;
        __nv_bfloat162 v2;
        v2.x = tile[tx * 2 + 0][n];
        v2.y = tile[tx * 2 + 1][n];
        *(uint32_t*)&db[(size_t)(n0 + n) * CCH + c0 + tx * 2] = *(uint32_t*)&v2;
    }
}

// ---------------- fp32 -> bf16 elementwise ----------------------------------
__global__ __launch_bounds__(256)
void f2bf_kernel(const float* __restrict__ src, bf16* __restrict__ dst) {
    size_t i = (size_t)blockIdx.x * blockDim.x + threadIdx.x;   // float4 index
    float4 v = ((const float4*)src)[i];
    __nv_bfloat162 lo = __floats2bfloat162_rn(v.x, v.y);
    __nv_bfloat162 hi = __floats2bfloat162_rn(v.z, v.w);
    ((__nv_bfloat162*)dst)[2 * i + 0] = lo;
    ((__nv_bfloat162*)dst)[2 * i + 1] = hi;
}

// ---------------- NT bf16 GEMM: D[r][c] = scale*sum_k A[r][k]B[c][k] + ... ---
// Block tile 128(M) x 128(N) x 32(K). 256 thr = 8 warps (2 M x 4 N).
// Warp tile 64x32: 4 m-frags (16) x 4 n-frags (8). cp.async 4-stage ring.
#define TILE_ROW 40   // padded row elems (80 B) -> conflict-free ldmatrix
#define STAGE_BYTES (128 * TILE_ROW * 2)   // 10240
#define NSTAGE 4
#define SMEM_TOTAL_GEMM (2 * NSTAGE * STAGE_BYTES)   // 81920

__global__ __launch_bounds__(256, 1)
void mma_gemm(const bf16* __restrict__ A, const bf16* __restrict__ B, void* __restrict__ D,
              size_t aBatch, size_t bBatch, size_t dBatch,
              int astride, int bstride, int dstride, int ksteps, float scale,
              const float* __restrict__ bias, int biasMode,
              const float* __restrict__ resid, int outF32, int expOut) {
    extern __shared__ __align__(16) char smem[];
    const uint32_t sA = smem_u32(smem);
    const uint32_t sB = sA + NSTAGE * STAGE_BYTES;

    const int t    = threadIdx.x;
    const int lane = t & 31;
    const int wid  = t >> 5;
    const int wm   = wid & 1;
    const int wn   = wid >> 1;
    const int bz   = blockIdx.z;
    const int row0 = blockIdx.y * 128;
    const int col0 = blockIdx.x * 128;

    const bf16* Abase = A + (size_t)bz * aBatch + (size_t)row0 * astride;
    const bf16* Bbase = B + (size_t)bz * bBatch + (size_t)col0 * bstride;

    const int lrow = t >> 2;
    const int lcu  = t & 3;

    float acc[4][4][4];
    #pragma unroll
    for (int i = 0; i < 4; i++)
        #pragma unroll
        for (int j = 0; j < 4; j++)
            #pragma unroll
            for (int r = 0; r < 4; r++) acc[i][j][r] = 0.f;

    // prologue: chunks 0..NSTAGE-2, one commit-group each
    #pragma unroll
    for (int s = 0; s < NSTAGE - 1; s++) {
        if (s < ksteps) {
            const int k0 = s * 32;
            const uint32_t st = (uint32_t)s * STAGE_BYTES;
            #pragma unroll
            for (int i = 0; i < 2; i++) {
                int row = lrow + i * 64;
                uint32_t soff = st + (uint32_t)(row * TILE_ROW + lcu * 8) * 2;
                cp_async16(sA + soff, Abase + (size_t)row * astride + k0 + lcu * 8);
                cp_async16(sB + soff, Bbase + (size_t)row * bstride + k0 + lcu * 8);
            }
        }
        CP_COMMIT();
    }

    for (int kt = 0; kt < ksteps; kt++) {
        {
            const int ci = kt + NSTAGE - 1;
            if (ci < ksteps) {
                const int k0 = ci * 32;
                const uint32_t st = (uint32_t)(ci & (NSTAGE - 1)) * STAGE_BYTES;
                #pragma unroll
                for (int i = 0; i < 2; i++) {
                    int row = lrow + i * 64;
                    uint32_t soff = st + (uint32_t)(row * TILE_ROW + lcu * 8) * 2;
                    cp_async16(sA + soff, Abase + (size_t)row * astride + k0 + lcu * 8);
                    cp_async16(sB + soff, Bbase + (size_t)row * bstride + k0 + lcu * 8);
                }
            }
            CP_COMMIT();           // always commit (empty group in tail)
            CP_WAIT(NSTAGE - 1);   // chunk kt complete
        }
        __syncthreads();

        const uint32_t aB = sA + (uint32_t)(kt & (NSTAGE - 1)) * STAGE_BYTES;
        const uint32_t bB = sB + (uint32_t)(kt & (NSTAGE - 1)) * STAGE_BYTES;
        #pragma unroll
        for (int ks = 0; ks < 2; ks++) {
            uint32_t afr[4][4], bfr[2][4];
            #pragma unroll
            for (int mf = 0; mf < 4; mf++) {
                uint32_t addr = aB + (uint32_t)((wm * 64 + mf * 16 + (lane & 15)) * (TILE_ROW * 2))
                              + (uint32_t)(ks * 32) + ((uint32_t)(lane >> 4) << 4);
                ldsm4(afr[mf], addr);
            }
            #pragma unroll
            for (int ng = 0; ng < 2; ng++) {
                uint32_t addr = bB + (uint32_t)((wn * 32 + ng * 16 + (lane & 7) + ((lane >> 4) & 1) * 8) * (TILE_ROW * 2))
                              + (uint32_t)(ks * 32) + ((uint32_t)((lane >> 3) & 1) << 4);
                ldsm4(bfr[ng], addr);
            }
            #pragma unroll
            for (int mf = 0; mf < 4; mf++)
                #pragma unroll
                for (int nf = 0; nf < 4; nf++)
                    mma16816(acc[mf][nf], afr[mf], &bfr[nf >> 1][(nf & 1) * 2]);
        }
        __syncthreads();
    }

    // epilogue
    const float* residb = resid ? resid + (size_t)bz * dBatch : nullptr;
    #pragma unroll
    for (int mf = 0; mf < 4; mf++) {
        int rbase = row0 + wm * 64 + mf * 16 + (lane >> 2);
        #pragma unroll
        for (int nf = 0; nf < 4; nf++) {
            int c = col0 + wn * 32 + nf * 8 + (lane & 3) * 2;
            #pragma unroll
            for (int h = 0; h < 2; h++) {
                int r = rbase + h * 8;
                float v0 = acc[mf][nf][h * 2 + 0] * scale;
                float v1 = acc[mf][nf][h * 2 + 1] * scale;
                if (biasMode == 1)      { float bv = bias[r]; v0 += bv; v1 += bv; }
                else if (biasMode == 2) { v0 += bias[c]; v1 += bias[c + 1]; }
                size_t idx = (size_t)r * dstride + c;
                if (outF32) {
                    if (residb) { v0 += residb[idx]; v1 += residb[idx + 1]; }
                    float2 f; f.x = v0; f.y = v1;
                    *(float2*)((float*)D + (size_t)bz * dBatch + idx) = f;
                } else {
                    if (expOut) { v0 = __expf(v0); v1 = __expf(v1); }
                    *(__nv_bfloat162*)((bf16*)D + (size_t)bz * dBatch + idx) =
                        __floats2bfloat162_rn(v0, v1);
                }
            }
        }
    }
}

// ---------------- AV GEMM with inline row-sum normalization ------------------
// ht[n][o] = (1/rowsum_n) * sum_m expS[n][m] * vb[o][m]
__global__ __launch_bounds__(256, 1)
void mma_av(const bf16* __restrict__ A, const bf16* __restrict__ B, bf16* __restrict__ D) {
    extern __shared__ __align__(16) char smem[];
    __shared__ float sumrow[128];
    const uint32_t sA = smem_u32(smem);
    const uint32_t sB = sA + NSTAGE * STAGE_BYTES;

    const int t    = threadIdx.x;
    const int lane = t & 31;
    const int wid  = t >> 5;
    const int wm   = wid & 1;
    const int wn   = wid >> 1;
    const int bz   = blockIdx.z;
    const int row0 = blockIdx.y * 128;
    const int col0 = blockIdx.x * 128;

    const bf16* Abase = A + (size_t)bz * NTOK * NTOK + (size_t)row0 * NTOK;
    const bf16* Bbase = B + (size_t)bz * CCH * NTOK + (size_t)col0 * NTOK;

    const int lrow = t >> 2;
    const int lcu  = t & 3;
    const int ksteps = NTOK / 32;   // 128

    float acc[4][4][4];
    #pragma unroll
    for (int i = 0; i < 4; i++)
        #pragma unroll
        for (int j = 0; j < 4; j++)
            #pragma unroll
            for (int r = 0; r < 4; r++) acc[i][j][r] = 0.f;
    float rs = 0.f;
    const int srow = t >> 1;            // 2 threads per A row for the row sum
    const int skoff = (t & 1) * 16;

    #pragma unroll
    for (int s = 0; s < NSTAGE - 1; s++) {
        const int k0 = s * 32;
        const uint32_t st = (uint32_t)s * STAGE_BYTES;
        #pragma unroll
        for (int i = 0; i < 2; i++) {
            int row = lrow + i * 64;
            uint32_t soff = st + (uint32_t)(row * TILE_ROW + lcu * 8) * 2;
            cp_async16(sA + soff, Abase + (size_t)row * NTOK + k0 + lcu * 8);
            cp_async16(sB + soff, Bbase + (size_t)row * NTOK + k0 + lcu * 8);
        }
        CP_COMMIT();
    }

    for (int kt = 0; kt < ksteps; kt++) {
        {
            const int ci = kt + NSTAGE - 1;
            if (ci < ksteps) {
                const int k0 = ci * 32;
                const uint32_t st = (uint32_t)(ci & (NSTAGE - 1)) * STAGE_BYTES;
                #pragma unroll
                for (int i = 0; i < 2; i++) {
                    int row = lrow + i * 64;
                    uint32_t soff = st + (uint32_t)(row * TILE_ROW + lcu * 8) * 2;
                    cp_async16(sA + soff, Abase + (size_t)row * NTOK + k0 + lcu * 8);
                    cp_async16(sB + soff, Bbase + (size_t)row * NTOK + k0 + lcu * 8);
                }
            }
            CP_COMMIT();
            CP_WAIT(NSTAGE - 1);
        }
        __syncthreads();

        const uint32_t aB = sA + (uint32_t)(kt & (NSTAGE - 1)) * STAGE_BYTES;
        const uint32_t bB = sB + (uint32_t)(kt & (NSTAGE - 1)) * STAGE_BYTES;
        #pragma unroll
        for (int ks = 0; ks < 2; ks++) {
            uint32_t afr[4][4], bfr[2][4];
            #pragma unroll
            for (int mf = 0; mf < 4; mf++) {
                uint32_t addr = aB + (uint32_t)((wm * 64 + mf * 16 + (lane & 15)) * (TILE_ROW * 2))
                              + (uint32_t)(ks * 32) + ((uint32_t)(lane >> 4) << 4);
                ldsm4(afr[mf], addr);
            }
            #pragma unroll
            for (int ng = 0; ng < 2; ng++) {
                uint32_t addr = bB + (uint32_t)((wn * 32 + ng * 16 + (lane & 7) + ((lane >> 4) & 1) * 8) * (TILE_ROW * 2))
                              + (uint32_t)(ks * 32) + ((uint32_t)((lane >> 3) & 1) << 4);
                ldsm4(bfr[ng], addr);
            }
            #pragma unroll
            for (int mf = 0; mf < 4; mf++)
                #pragma unroll
                for (int nf = 0; nf < 4; nf++)
                    mma16816(acc[mf][nf], afr[mf], &bfr[nf >> 1][(nf & 1) * 2]);
        }

        // inline row-sum of this A (expS) stage: deterministic per-thread order
        {
            const bf16* arow = (const bf16*)(smem
                + (size_t)(kt & (NSTAGE - 1)) * STAGE_BYTES)
                + srow * TILE_ROW + skoff;
            float part = 0.f;
            #pragma unroll
            for (int j = 0; j < 8; j++) {
                __nv_bfloat162 u = *(const __nv_bfloat162*)&arow[2 * j];
                part += __bfloat162float(u.x) + __bfloat162float(u.y);
            }
            rs += part;
        }
        __syncthreads();
    }

    // combine row-sum halves (lanes t, t^1 adjacent in same warp)
    rs += __shfl_xor_sync(0xffffffffu, rs, 1);
    if ((t & 1) == 0) sumrow[srow] = rs;
    __syncthreads();

    // epilogue: normalize rows, write bf16
    bf16* Db = D + (size_t)bz * NTOK * CCH;
    #pragma unroll
    for (int mf = 0; mf < 4; mf++) {
        int rloc = wm * 64 + mf * 16 + (lane >> 2);
        #pragma unroll
        for (int nf = 0; nf < 4; nf++) {
            int c = col0 + wn * 32 + nf * 8 + (lane & 3) * 2;
            #pragma unroll
            for (int h = 0; h < 2; h++) {
                int rl = rloc + h * 8;
                float inv = 1.f / sumrow[rl];
                float v0 = acc[mf][nf][h * 2 + 0] * inv;
                float v1 = acc[mf][nf][h * 2 + 1] * inv;
                *(__nv_bfloat162*)&Db[(size_t)(row0 + rl) * CCH + c] =
                    __floats2bfloat162_rn(v0, v1);
            }
        }
    }
}

// ---------------- launch ------------------------------------------------------
extern "C" void kernel_launch(void* const* d_in, const int* in_sizes, int n_in,
                              void* d_out, int out_size) {
    const float* x     = (const float*)d_in[0];
    const float* gns   = (const float*)d_in[1];
    const float* gnb   = (const float*)d_in[2];
    const float* wq    = (const float*)d_in[3];
    const float* bq    = (const float*)d_in[4];
    const float* wk    = (const float*)d_in[5];
    const float* bk    = (const float*)d_in[6];
    const float* wv    = (const float*)d_in[7];
    const float* bv    = (const float*)d_in[8];
    const float* wproj = (const float*)d_in[9];
    const float* bproj = (const float*)d_in[10];
    float* out = (float*)d_out;

    bf16 *hnb, *hnT, *qt, *kt, *vb, *ht, *p, *wqb, *wkb, *wvb, *wpb;
    cudaGetSymbolAddress((void**)&hnb, g_hnb);
    cudaGetSymbolAddress((void**)&hnT, g_hnT);
    cudaGetSymbolAddress((void**)&qt,  g_qt);
    cudaGetSymbolAddress((void**)&kt,  g_kt);
    cudaGetSymbolAddress((void**)&vb,  g_vb);
    cudaGetSymbolAddress((void**)&ht,  g_ht);
    cudaGetSymbolAddress((void**)&p,   g_p);
    cudaGetSymbolAddress((void**)&wqb, g_wqb);
    cudaGetSymbolAddress((void**)&wkb, g_wkb);
    cudaGetSymbolAddress((void**)&wvb, g_wvb);
    cudaGetSymbolAddress((void**)&wpb, g_wpb);

    cudaFuncSetAttribute(mma_gemm, cudaFuncAttributeMaxDynamicSharedMemorySize, SMEM_TOTAL_GEMM);
    cudaFuncSetAttribute(mma_av,   cudaFuncAttributeMaxDynamicSharedMemorySize, SMEM_TOTAL_GEMM);

    const size_t CN = (size_t)CCH * NTOK;
    const size_t NN = (size_t)NTOK * NTOK;

    // 1. GroupNorm -> bf16 [c][n]
    gn_kernel<<<BBATCH * NG, 256>>>(x, gns, gnb);

    // 2. transpose -> hnT [n][c]
    dim3 gt(NTOK / 64, CCH / 64, BBATCH);
    transpose_kernel<<<gt, 256>>>(hnb, hnT);

    // 3. weights -> bf16
    f2bf_kernel<<<64, 256>>>(wq,    wqb);
    f2bf_kernel<<<64, 256>>>(wk,    wkb);
    f2bf_kernel<<<64, 256>>>(wv,    wvb);
    f2bf_kernel<<<64, 256>>>(wproj, wpb);

    // 4. qt[n][o] = hnT . Wq^T + bq   (bias per-col)
    dim3 gq(CCH / 128, NTOK / 128, BBATCH);
    mma_gemm<<<gq, 256, SMEM_TOTAL_GEMM>>>(hnT, wqb, qt, CN, 0, CN, CCH, CCH, CCH, CCH / 32, 1.f, bq, 2, nullptr, 0, 0);
    mma_gemm<<<gq, 256, SMEM_TOTAL_GEMM>>>(hnT, wkb, kt, CN, 0, CN, CCH, CCH, CCH, CCH / 32, 1.f, bk, 2, nullptr, 0, 0);

    // 5. vb[o][m] = Wv . hnT^T + bv   (bias per-row)
    dim3 gv(NTOK / 128, CCH / 128, BBATCH);
    mma_gemm<<<gv, 256, SMEM_TOTAL_GEMM>>>(wvb, hnT, vb, 0, CN, CN, CCH, CCH, NTOK, CCH / 32, 1.f, bv, 1, nullptr, 0, 0);

    // 6. expS[n][m] = exp((1/16) qt . kt^T)  -> bf16
    dim3 gs(NTOK / 128, NTOK / 128, BBATCH);
    mma_gemm<<<gs, 256, SMEM_TOTAL_GEMM>>>(qt, kt, p, CN, CN, NN, CCH, CCH, NTOK, CCH / 32, 0.0625f,
                          nullptr, 0, nullptr, 0, 1);

    // 7. ht[n][o] = softmax-normalized expS . vb^T  (row sums inline)
    dim3 gh(CCH / 128, NTOK / 128, BBATCH);
    mma_av<<<gh, 256, SMEM_TOTAL_GEMM>>>(p, vb, ht);

    // 8. out[o][n] = Wproj . ht^T + bproj + x   (fp32 out + residual)
    dim3 go(NTOK / 128, CCH / 128, BBATCH);
    mma_gemm<<<go, 256, SMEM_TOTAL_GEMM>>>(wpb, ht, out, 0, CN, CN, CCH, CCH, NTOK, CCH / 32, 1.f,
                          bproj, 1, x, 1, 0);
}